// round 14
// baseline (speedup 1.0000x reference)
#include <cuda_runtime.h>
#include <math.h>
#include <stdint.h>

// ---------------- problem constants ----------------
#define NTOK      8192            // B*S = 4*2048
#define D_MODEL   1024
#define N_EXPERTS 8
#define N_FEAT    16
#define RAW_FEAT  512
#define PROJ_DIM  256
#define R_IN      1280
#define R_HID     256
#define E_HID     256
#define MARGIN    1.5e-3f

// output layout (floats) : next_hidden | stage_out | gate | scaled_logits | group | rule
#define OFF_STAGE 8388608ull
#define OFF_GATE  16777216ull
#define OFF_SLOG  16842752ull
#define OFF_GRP   16908288ull
#define OFF_RULE  16941056ull

// ---------------- device scratch (no allocations allowed) ----------------
__device__ float g_hnorm[(size_t)NTOK * D_MODEL];
__device__ float g_P1   [(size_t)NTOK * PROJ_DIM];
__device__ float g_XA1  [(size_t)NTOK * R_HID];
__device__ float g_XA2  [(size_t)NTOK * R_HID];
__device__ float g_RHs  [(size_t)NTOK * R_HID];
__device__ float g_Wc   [PROJ_DIM * R_HID];
__device__ float g_cc   [R_HID];
__device__ float g_H1   [(size_t)N_EXPERTS * NTOK * E_HID];
__device__ int   g_tok  [N_EXPERTS * NTOK];
__device__ float g_wt   [N_EXPERTS * NTOK];
__device__ int   g_cnt  [N_EXPERTS];
__device__ int   g_flag [NTOK];
__device__ int   g_nflag;

// ---------------- helpers ----------------
__device__ __forceinline__ float gelu_tanh(float x) {
    float x3 = x * x * x;
    return 0.5f * x * (1.0f + tanhf(0.7978845608028654f * (x + 0.044715f * x3)));
}
__device__ __forceinline__ uint32_t f2tf32(float x) {
    uint32_t r;
    asm("cvt.rna.tf32.f32 %0, %1;" : "=r"(r) : "f"(x));
    return r;
}
__device__ __forceinline__ void mma_tf32(float* c, const uint32_t* a, const uint32_t* b) {
    asm volatile(
        "mma.sync.aligned.m16n8k8.row.col.f32.tf32.tf32.f32 "
        "{%0,%1,%2,%3}, {%4,%5,%6,%7}, {%8,%9}, {%0,%1,%2,%3};"
        : "+f"(c[0]), "+f"(c[1]), "+f"(c[2]), "+f"(c[3])
        : "r"(a[0]), "r"(a[1]), "r"(a[2]), "r"(a[3]), "r"(b[0]), "r"(b[1]));
}

// ================= shared tf32 mma tile: 128x64, K-chunk 32, 256 threads =================
// A: row-major (m0+row, k), lda. B: row-major (k, n0+col), ldb. acc[2][4][4] per thread.
__device__ __forceinline__ void mma_tile(
    const float* __restrict__ A, int lda,
    const float* __restrict__ B, int ldb,
    int m0, int n0, int K,
    uint32_t* __restrict__ smA, uint32_t* __restrict__ smB,
    float acc[2][4][4])
{
    const int t = threadIdx.x;
    const int arow_l = t >> 1;
    const int aks    = (t & 1) * 16;
    const int ami    = arow_l >> 4;
    const int ar     = arow_l & 15;
    const int albase = (ar & 7) * 4;
    const int aslotr = (ar >> 3);
    const float* Ab = A + (size_t)(m0 + arow_l) * lda + aks;

    const int bkrow = t >> 3;
    const int bns   = (t & 7) * 8;
    const int bki   = bkrow >> 3;
    const int bc    = bkrow & 7;
    const int bslot = bc >> 2;
    const int blc2  = (bc & 3) * 2;
    const int bni   = t & 7;
    const float* Bb = B + (size_t)bkrow * ldb + n0 + bns;

    const int lane = t & 31;
    const int wid  = t >> 5;
    const int wm   = wid >> 1;
    const int wn   = wid & 1;

#pragma unroll
    for (int i = 0; i < 2; i++)
#pragma unroll
        for (int j = 0; j < 4; j++)
#pragma unroll
            for (int q = 0; q < 4; q++) acc[i][j][q] = 0.f;

    float4 av[4], bv[2];

#define LOAD_GMEM(C0) do {                                                       \
        size_t kof = (size_t)(C0) * 32;                                          \
        av[0] = *reinterpret_cast<const float4*>(Ab + kof);                      \
        av[1] = *reinterpret_cast<const float4*>(Ab + kof + 4);                  \
        av[2] = *reinterpret_cast<const float4*>(Ab + kof + 8);                  \
        av[3] = *reinterpret_cast<const float4*>(Ab + kof + 12);                 \
        bv[0] = *reinterpret_cast<const float4*>(Bb + kof * ldb);                \
        bv[1] = *reinterpret_cast<const float4*>(Bb + kof * ldb + 4);            \
    } while (0)

#define STAGE(BF) do {                                                           \
        uint32_t* Ax = smA + (BF) * 4096;                                        \
        uint32_t* Bx = smB + (BF) * 2048;                                        \
        _Pragma("unroll")                                                        \
        for (int q = 0; q < 4; q++) {                                            \
            int kl  = aks + 4 * q;                                               \
            int fb  = (ami * 4 + (kl >> 3)) * 128 + albase * 4                   \
                    + aslotr + (((kl >> 2) & 1) << 1);                           \
            const float* pv = &av[q].x;                                          \
            _Pragma("unroll")                                                    \
            for (int j = 0; j < 4; j++) Ax[fb + 4 * j] = f2tf32(pv[j]);          \
        }                                                                        \
        _Pragma("unroll")                                                        \
        for (int h = 0; h < 2; h++) {                                            \
            int fb = (bki * 8 + bni) * 64 + (h * 4) * 8 + blc2 + bslot;          \
            const float* pv = &bv[h].x;                                          \
            _Pragma("unroll")                                                    \
            for (int j = 0; j < 4; j++) Bx[fb + 8 * j] = f2tf32(pv[j]);          \
        }                                                                        \
    } while (0)

#define COMPUTE(BF) do {                                                         \
        const uint32_t* Ax = smA + (BF) * 4096;                                  \
        const uint32_t* Bx = smB + (BF) * 2048;                                  \
        _Pragma("unroll")                                                        \
        for (int ki = 0; ki < 4; ki++) {                                         \
            uint32_t afr[2][4], bfr[4][2];                                       \
            _Pragma("unroll")                                                    \
            for (int ml = 0; ml < 2; ml++)                                       \
                *reinterpret_cast<uint4*>(afr[ml]) =                             \
                    *reinterpret_cast<const uint4*>(                             \
                        Ax + ((wm * 2 + ml) * 4 + ki) * 128 + lane * 4);         \
            _Pragma("unroll")                                                    \
            for (int nl = 0; nl < 4; nl++)                                       \
                *reinterpret_cast<uint2*>(bfr[nl]) =                             \
                    *reinterpret_cast<const uint2*>(                             \
                        Bx + (ki * 8 + wn * 4 + nl) * 64 + lane * 2);            \
            _Pragma("unroll")                                                    \
            for (int ml = 0; ml < 2; ml++)                                       \
                _Pragma("unroll")                                                \
                for (int nl = 0; nl < 4; nl++)                                   \
                    mma_tf32(acc[ml][nl], afr[ml], bfr[nl]);                     \
        }                                                                        \
    } while (0)

    const int NC = K / 32;
    LOAD_GMEM(0);
    STAGE(0);
    __syncthreads();
    int buf = 0;
    for (int c = 1; c < NC; c++) {
        LOAD_GMEM(c);
        COMPUTE(buf);
        STAGE(buf ^ 1);
        __syncthreads();
        buf ^= 1;
    }
    COMPUTE(buf);
#undef LOAD_GMEM
#undef STAGE
#undef COMPUTE
}

// ================= K1: layernorm + init =================
__global__ __launch_bounds__(256) void k_layernorm(
    const float* __restrict__ hidden,
    const float* __restrict__ ln_g,
    const float* __restrict__ ln_b,
    float* __restrict__ out)
{
    int t   = blockIdx.x;
    int tid = threadIdx.x;
    const float* x = hidden + (size_t)t * D_MODEL;

    float v[4], s = 0.f, s2 = 0.f;
#pragma unroll
    for (int j = 0; j < 4; j++) {
        v[j] = x[tid + 256 * j];
        s  += v[j];
        s2 += v[j] * v[j];
    }
#pragma unroll
    for (int o = 16; o; o >>= 1) {
        s  += __shfl_down_sync(0xffffffffu, s,  o);
        s2 += __shfl_down_sync(0xffffffffu, s2, o);
    }
    __shared__ float ps[8], ps2[8];
    __shared__ float mu_s, rs_s;
    int w = tid >> 5, l = tid & 31;
    if (l == 0) { ps[w] = s; ps2[w] = s2; }
    __syncthreads();
    if (tid == 0) {
        float S = 0.f, S2 = 0.f;
#pragma unroll
        for (int i = 0; i < 8; i++) { S += ps[i]; S2 += ps2[i]; }
        float mu  = S * (1.0f / D_MODEL);
        float var = S2 * (1.0f / D_MODEL) - mu * mu;
        mu_s = mu;
        rs_s = rsqrtf(var + 1e-5f);
    }
    __syncthreads();
    float mu = mu_s, rs = rs_s;
#pragma unroll
    for (int j = 0; j < 4; j++) {
        int d = tid + 256 * j;
        float hn = (v[j] - mu) * rs * ln_g[d] + ln_b[d];
        g_hnorm[(size_t)t * D_MODEL + d] = hn;
        out[OFF_STAGE + (size_t)t * D_MODEL + d] = 0.0f;
    }
    if (t == 0 && tid < N_EXPERTS) g_cnt[tid] = 0;
    if (t == 0 && tid == 0) g_nflag = 0;
}

// ================= K2: multiplexed tf32 router GEMMs =================
// z=0: P1  = gelu(bank @ fp_w1 + fp_b1)
// z=1: XA1 = hnorm[:, :512]  @ r_w1[0:512]   + r_b1
// z=2: XA2 = hnorm[:, 512:]  @ r_w1[512:1024]
// z=3: Wc  = fp_w2 @ r_w1[1024:] (bx<2); cc = fp_b2 @ r_w1[1024:] (bx==2,by==0)
__global__ __launch_bounds__(256, 2) void k_mma_router(
    const float* __restrict__ bank,
    const float* __restrict__ fp_w1, const float* __restrict__ fp_b1,
    const float* __restrict__ fp_w2, const float* __restrict__ fp_b2,
    const float* __restrict__ r_w1,  const float* __restrict__ r_b1)
{
    __shared__ uint32_t sm[12288];
    const int z  = blockIdx.z;
    const int bx = blockIdx.x, by = blockIdx.y;

    const float* A; int lda; const float* B; const float* bias;
    float* C; int K; int act;
    if (z == 0) {
        A = bank; lda = RAW_FEAT; B = fp_w1; bias = fp_b1;
        C = g_P1; K = RAW_FEAT; act = 1;
    } else if (z == 1) {
        A = g_hnorm; lda = D_MODEL; B = r_w1; bias = r_b1;
        C = g_XA1; K = 512; act = 0;
    } else if (z == 2) {
        A = g_hnorm + 512; lda = D_MODEL; B = r_w1 + 512 * R_HID; bias = nullptr;
        C = g_XA2; K = 512; act = 0;
    } else {
        if (bx == 2 && by == 0) {
            int j = threadIdx.x;
            float s = 0.f;
            for (int k = 0; k < PROJ_DIM; k++)
                s = fmaf(fp_b2[k], r_w1[(size_t)(D_MODEL + k) * R_HID + j], s);
            g_cc[j] = s;
            return;
        }
        if (bx >= 2) return;
        A = fp_w2; lda = PROJ_DIM; B = r_w1 + (size_t)D_MODEL * R_HID; bias = nullptr;
        C = g_Wc; K = PROJ_DIM; act = 0;
    }

    const int m0 = bx * 128, n0 = by * 64;
    float acc[2][4][4];
    mma_tile(A, lda, B, R_HID, m0, n0, K, sm, sm + 8192, acc);

    const int lane = threadIdx.x & 31, wid = threadIdx.x >> 5;
    const int wm = wid >> 1, wn = wid & 1;
    const int gr = lane >> 2, gc = (lane & 3) * 2;
#pragma unroll
    for (int ml = 0; ml < 2; ml++) {
#pragma unroll
        for (int nl = 0; nl < 4; nl++) {
            int col = wn * 32 + nl * 8 + gc;
            float b0 = bias ? bias[n0 + col]     : 0.f;
            float b1 = bias ? bias[n0 + col + 1] : 0.f;
#pragma unroll
            for (int h = 0; h < 2; h++) {
                int m = m0 + wm * 32 + ml * 16 + gr + h * 8;
                float x0 = acc[ml][nl][h * 2 + 0] + b0;
                float x1 = acc[ml][nl][h * 2 + 1] + b1;
                if (act) { x0 = gelu_tanh(x0); x1 = gelu_tanh(x1); }
                *reinterpret_cast<float2*>(&C[(size_t)m * R_HID + n0 + col]) =
                    make_float2(x0, x1);
            }
        }
    }
}

// ================= K4b: RH = gelu(P1 @ Wc + cc + XA1 + XA2) =================
__global__ __launch_bounds__(256, 2) void k_4b_mma()
{
    __shared__ uint32_t sm[12288];
    const int m0 = blockIdx.x * 128, n0 = blockIdx.y * 64;
    float acc[2][4][4];
    mma_tile(g_P1, PROJ_DIM, g_Wc, R_HID, m0, n0, PROJ_DIM, sm, sm + 8192, acc);

    const int lane = threadIdx.x & 31, wid = threadIdx.x >> 5;
    const int wm = wid >> 1, wn = wid & 1;
    const int gr = lane >> 2, gc = (lane & 3) * 2;
#pragma unroll
    for (int ml = 0; ml < 2; ml++) {
#pragma unroll
        for (int nl = 0; nl < 4; nl++) {
            int colg = n0 + wn * 32 + nl * 8 + gc;
            float c0 = g_cc[colg], c1 = g_cc[colg + 1];
#pragma unroll
            for (int h = 0; h < 2; h++) {
                int m = m0 + wm * 32 + ml * 16 + gr + h * 8;
                float2 u1 = *reinterpret_cast<const float2*>(&g_XA1[(size_t)m * R_HID + colg]);
                float2 u2 = *reinterpret_cast<const float2*>(&g_XA2[(size_t)m * R_HID + colg]);
                float x0 = acc[ml][nl][h * 2 + 0] + c0 + u1.x + u2.x;
                float x1 = acc[ml][nl][h * 2 + 1] + c1 + u1.y + u2.y;
                *reinterpret_cast<float2*>(&g_RHs[(size_t)m * R_HID + colg]) =
                    make_float2(gelu_tanh(x0), gelu_tanh(x1));
            }
        }
    }
}

// ================= K5: router logits, top-2 softmax, flagging, dispatch =================
__global__ __launch_bounds__(256) void k_router(
    const float* __restrict__ r_w2, const float* __restrict__ r_b2,
    const float* __restrict__ feat,
    const float* __restrict__ rr_w, const float* __restrict__ rr_b,
    float* __restrict__ out)
{
    int w = threadIdx.x >> 5, l = threadIdx.x & 31;
    int t = blockIdx.x * 8 + w;
    const float* rh = g_RHs + (size_t)t * R_HID;

    float acc[8] = {};
    for (int k = l; k < R_HID; k += 32) {
        float v = rh[k];
#pragma unroll
        for (int e = 0; e < 8; e++) acc[e] = fmaf(v, r_w2[k * 8 + e], acc[e]);
    }
#pragma unroll
    for (int o = 16; o; o >>= 1)
#pragma unroll
        for (int e = 0; e < 8; e++) acc[e] += __shfl_down_sync(0xffffffffu, acc[e], o);

    if (l == 0) {
        float lg[8];
#pragma unroll
        for (int e = 0; e < 8; e++) lg[e] = acc[e] + r_b2[e];

        // rule logits: exact fp32, written for ALL tokens
        float fv[16];
#pragma unroll
        for (int i = 0; i < 16; i++) fv[i] = feat[(size_t)t * 16 + i];
#pragma unroll
        for (int e = 0; e < 8; e++) {
            float r = rr_b[e];
#pragma unroll
            for (int i = 0; i < 16; i++) r = fmaf(fv[i], rr_w[i * 8 + e], r);
            out[OFF_RULE + (size_t)t * 8 + e] = r;
        }

        // top-3
        int i1 = 0; float m1 = lg[0];
#pragma unroll
        for (int e = 1; e < 8; e++) if (lg[e] > m1) { m1 = lg[e]; i1 = e; }
        int i2 = -1; float m2 = -3.4e38f;
#pragma unroll
        for (int e = 0; e < 8; e++) if (e != i1 && lg[e] > m2) { m2 = lg[e]; i2 = e; }
        float m3 = -3.4e38f;
#pragma unroll
        for (int e = 0; e < 8; e++) if (e != i1 && e != i2 && lg[e] > m3) m3 = lg[e];

        if (m2 - m3 < MARGIN) {
            int fi = atomicAdd(&g_nflag, 1);
            g_flag[fi] = t;
        } else {
            float Z = 0.f, g[8];
#pragma unroll
            for (int e = 0; e < 8; e++) {
                if (lg[e] >= m2) { g[e] = expf(lg[e] - m1); Z += g[e]; }
                else g[e] = 0.f;
            }
            float invZ = 1.0f / Z;
#pragma unroll
            for (int e = 0; e < 8; e++) {
                g[e] *= invZ;
                out[OFF_GATE + (size_t)t * 8 + e] = g[e];
                out[OFF_SLOG + (size_t)t * 8 + e] = lg[e];
            }
#pragma unroll
            for (int gi = 0; gi < 4; gi++)
                out[OFF_GRP + (size_t)t * 4 + gi] = g[2 * gi] + g[2 * gi + 1];
#pragma unroll
            for (int e = 0; e < 8; e++) {
                if (g[e] > 0.f) {
                    int p = atomicAdd(&g_cnt[e], 1);
                    g_tok[e * NTOK + p] = t;
                    g_wt [e * NTOK + p] = g[e];
                }
            }
        }
    }
}

// ================= K5b: exact fp32 fallback for ambiguous tokens =================
__global__ __launch_bounds__(256) void k_fallback(
    const float* __restrict__ bank,
    const float* __restrict__ fp_w1, const float* __restrict__ fp_b1,
    const float* __restrict__ fp_w2, const float* __restrict__ fp_b2,
    const float* __restrict__ r_w1,  const float* __restrict__ r_b1,
    const float* __restrict__ r_w2,  const float* __restrict__ r_b2,
    float* __restrict__ out)
{
    __shared__ float h1p[256], proj_s[256], rh_s[256], lgs[8];
    const int j = threadIdx.x;
    const int nf = g_nflag;

    for (int i = blockIdx.x; i < nf; i += gridDim.x) {
        int t = g_flag[i];
        // P1 row (exact fp32)
        const float* bk = bank + (size_t)t * RAW_FEAT;
        float s = fp_b1[j];
        for (int k = 0; k < RAW_FEAT; k++)
            s = fmaf(bk[k], fp_w1[(size_t)k * PROJ_DIM + j], s);
        h1p[j] = gelu_tanh(s);
        __syncthreads();
        // proj row
        float p = fp_b2[j];
        for (int k = 0; k < PROJ_DIM; k++)
            p = fmaf(h1p[k], fp_w2[(size_t)k * PROJ_DIM + j], p);
        proj_s[j] = p;
        __syncthreads();
        // RH row
        const float* hn = g_hnorm + (size_t)t * D_MODEL;
        float rh = r_b1[j];
        for (int k = 0; k < D_MODEL; k++)
            rh = fmaf(hn[k], r_w1[(size_t)k * R_HID + j], rh);
        for (int k = 0; k < PROJ_DIM; k++)
            rh = fmaf(proj_s[k], r_w1[(size_t)(D_MODEL + k) * R_HID + j], rh);
        rh_s[j] = gelu_tanh(rh);
        __syncthreads();
        // logits: warp e computes lg[e]
        int w = j >> 5, l = j & 31;
        float a = 0.f;
        for (int k = l; k < R_HID; k += 32)
            a = fmaf(rh_s[k], r_w2[k * 8 + w], a);
#pragma unroll
        for (int o = 16; o; o >>= 1) a += __shfl_down_sync(0xffffffffu, a, o);
        if (l == 0) lgs[w] = a + r_b2[w];
        __syncthreads();
        if (j == 0) {
            float lg[8];
#pragma unroll
            for (int e = 0; e < 8; e++) lg[e] = lgs[e];
            int i1 = 0; float m1 = lg[0];
#pragma unroll
            for (int e = 1; e < 8; e++) if (lg[e] > m1) { m1 = lg[e]; i1 = e; }
            float m2 = -3.4e38f;
#pragma unroll
            for (int e = 0; e < 8; e++) if (e != i1 && lg[e] > m2) m2 = lg[e];
            float Z = 0.f, g[8];
#pragma unroll
            for (int e = 0; e < 8; e++) {
                if (lg[e] >= m2) { g[e] = expf(lg[e] - m1); Z += g[e]; }
                else g[e] = 0.f;
            }
            float invZ = 1.0f / Z;
#pragma unroll
            for (int e = 0; e < 8; e++) {
                g[e] *= invZ;
                out[OFF_GATE + (size_t)t * 8 + e] = g[e];
                out[OFF_SLOG + (size_t)t * 8 + e] = lg[e];
            }
#pragma unroll
            for (int gi = 0; gi < 4; gi++)
                out[OFF_GRP + (size_t)t * 4 + gi] = g[2 * gi] + g[2 * gi + 1];
#pragma unroll
            for (int e = 0; e < 8; e++) {
                if (g[e] > 0.f) {
                    int pp = atomicAdd(&g_cnt[e], 1);
                    g_tok[e * NTOK + pp] = t;
                    g_wt [e * NTOK + pp] = g[e];
                }
            }
        }
        __syncthreads();
    }
}

// ================= expert GEMMs via mma.sync TF32 (proven in R11/R12) =================
#define EXP_SMEM_BYTES (12544 * 4)

template<int MODE>
__global__ __launch_bounds__(256, 2) void k_expert_mma(
    const float* __restrict__ Asrc, const float* __restrict__ Bsrc,
    const float* __restrict__ bias, float* __restrict__ C,
    int K, int Ntot)
{
    extern __shared__ uint32_t sm[];
    uint32_t* smA = sm;
    uint32_t* smB = sm + 8192;
    int*      tok_s = (int*)(sm + 12288);
    float*    wt_s  = (float*)(sm + 12416);

    const int t   = threadIdx.x;
    const int e   = blockIdx.z;
    const int m0  = blockIdx.x * 128;
    const int n0  = blockIdx.y * 64;
    const int M   = g_cnt[e];
    if (m0 >= M) return;

    const float* Ae = (MODE == 1) ? Asrc : Asrc + (size_t)e * NTOK * K;
    const float* Be = Bsrc + (size_t)e * K * Ntot + n0;
    const float* be = bias + e * Ntot + n0;

    if (t < 128) {
        int idx = e * NTOK + min(m0 + t, M - 1);
        tok_s[t] = g_tok[idx];
        if (MODE == 2) wt_s[t] = g_wt[idx];
    }
    __syncthreads();

    const int arow_l = t >> 1;
    const int aks    = (t & 1) * 16;
    const int ami    = arow_l >> 4;
    const int ar     = arow_l & 15;
    const int albase = (ar & 7) * 4;
    const int aslotr = (ar >> 3);
    size_t arow_g;
    if (MODE == 1) arow_g = (size_t)tok_s[arow_l] * (size_t)K;
    else           arow_g = (size_t)min(m0 + arow_l, M - 1) * (size_t)K;
    const float* Ab = Ae + arow_g + aks;

    const int bkrow = t >> 3;
    const int bns   = (t & 7) * 8;
    const int bki   = bkrow >> 3;
    const int bc    = bkrow & 7;
    const int bslot = bc >> 2;
    const int blc2  = (bc & 3) * 2;
    const int bni   = t & 7;
    const float* Bb = Be + (size_t)bkrow * Ntot + bns;

    const int lane = t & 31;
    const int wid  = t >> 5;
    const int wm   = wid >> 1;
    const int wn   = wid & 1;

    float acc[2][4][4];
#pragma unroll
    for (int i = 0; i < 2; i++)
#pragma unroll
        for (int j = 0; j < 4; j++)
#pragma unroll
            for (int q = 0; q < 4; q++) acc[i][j][q] = 0.f;

    float4 av[4], bv[2];

#define LOAD_GMEM(C0) do {                                                       \
        size_t kof = (size_t)(C0) * 32;                                          \
        av[0] = *reinterpret_cast<const float4*>(Ab + kof);                      \
        av[1] = *reinterpret_cast<const float4*>(Ab + kof + 4);                  \
        av[2] = *reinterpret_cast<const float4*>(Ab + kof + 8);                  \
        av[3] = *reinterpret_cast<const float4*>(Ab + kof + 12);                 \
        bv[0] = *reinterpret_cast<const float4*>(Bb + kof * Ntot);               \
        bv[1] = *reinterpret_cast<const float4*>(Bb + kof * Ntot + 4);           \
    } while (0)

#define STAGE(BF) do {                                                           \
        uint32_t* A = smA + (BF) * 4096;                                         \
        uint32_t* B = smB + (BF) * 2048;                                         \
        _Pragma("unroll")                                                        \
        for (int q = 0; q < 4; q++) {                                            \
            int kl  = aks + 4 * q;                                               \
            int fb  = (ami * 4 + (kl >> 3)) * 128 + albase * 4                   \
                    + aslotr + (((kl >> 2) & 1) << 1);                           \
            const float* pv = &av[q].x;                                          \
            _Pragma("unroll")                                                    \
            for (int j = 0; j < 4; j++) A[fb + 4 * j] = f2tf32(pv[j]);           \
        }                                                                        \
        _Pragma("unroll")                                                        \
        for (int h = 0; h < 2; h++) {                                            \
            int fb = (bki * 8 + bni) * 64 + (h * 4) * 8 + blc2 + bslot;          \
            const float* pv = &bv[h].x;                                          \
            _Pragma("unroll")                                                    \
            for (int j = 0; j < 4; j++) B[fb + 8 * j] = f2tf32(pv[j]);           \
        }                                                                        \
    } while (0)

#define COMPUTE(BF) do {                                                         \
        const uint32_t* A = smA + (BF) * 4096;                                   \
        const uint32_t* B = smB + (BF) * 2048;                                   \
        _Pragma("unroll")                                                        \
        for (int ki = 0; ki < 4; ki++) {                                         \
            uint32_t afr[2][4], bfr[4][2];                                       \
            _Pragma("unroll")                                                    \
            for (int ml = 0; ml < 2; ml++)                                       \
                *reinterpret_cast<uint4*>(afr[ml]) =                             \
                    *reinterpret_cast<const uint4*>(                             \
                        A + ((wm * 2 + ml) * 4 + ki) * 128 + lane * 4);          \
            _Pragma("unroll")                                                    \
            for (int nl = 0; nl < 4; nl++)                                       \
                *reinterpret_cast<uint2*>(bfr[nl]) =                             \
                    *reinterpret_cast<const uint2*>(                             \
                        B + (ki * 8 + wn * 4 + nl) * 64 + lane * 2);             \
            _Pragma("unroll")                                                    \
            for (int ml = 0; ml < 2; ml++)                                       \
                _Pragma("unroll")                                                \
                for (int nl = 0; nl < 4; nl++)                                   \
                    mma_tf32(acc[ml][nl], afr[ml], bfr[nl]);                     \
        }                                                                        \
    } while (0)

    const int NC = K / 32;
    LOAD_GMEM(0);
    STAGE(0);
    __syncthreads();
    int buf = 0;
    for (int c = 1; c < NC; c++) {
        LOAD_GMEM(c);
        COMPUTE(buf);
        STAGE(buf ^ 1);
        __syncthreads();
        buf ^= 1;
    }
    COMPUTE(buf);

    const int gr = lane >> 2;
    const int gc = (lane & 3) * 2;
#pragma unroll
    for (int ml = 0; ml < 2; ml++) {
        int r0 = wm * 32 + ml * 16 + gr;
#pragma unroll
        for (int nl = 0; nl < 4; nl++) {
            int col = wn * 32 + nl * 8 + gc;
            float b0 = be[col], b1 = be[col + 1];
#pragma unroll
            for (int h = 0; h < 2; h++) {
                int rl = r0 + h * 8;
                int m  = m0 + rl;
                if (m < M) {
                    float x0 = acc[ml][nl][h * 2 + 0] + b0;
                    float x1 = acc[ml][nl][h * 2 + 1] + b1;
                    if (MODE == 1) {
                        float2 v = make_float2(gelu_tanh(x0), gelu_tanh(x1));
                        *reinterpret_cast<float2*>(
                            C + ((size_t)e * NTOK + m) * Ntot + n0 + col) = v;
                    } else {
                        int   tok = tok_s[rl];
                        float wgt = wt_s[rl];
                        float* dst = C + (size_t)tok * D_MODEL + n0 + col;
                        atomicAdd(&dst[0], x0 * wgt);
                        atomicAdd(&dst[1], x1 * wgt);
                    }
                }
            }
        }
    }
#undef LOAD_GMEM
#undef STAGE
#undef COMPUTE
}

// ================= K8: next_hidden = hidden + alpha * stage_out =================
__global__ __launch_bounds__(256) void k_finalize(
    const float* __restrict__ hidden,
    const float* __restrict__ alpha,
    float* __restrict__ out)
{
    size_t i = ((size_t)blockIdx.x * 256 + threadIdx.x) * 4;
    float a = alpha[0];
    float4 h = *reinterpret_cast<const float4*>(hidden + i);
    float4 s = *reinterpret_cast<const float4*>(out + OFF_STAGE + i);
    float4 r;
    r.x = h.x + a * s.x;
    r.y = h.y + a * s.y;
    r.z = h.z + a * s.z;
    r.w = h.w + a * s.w;
    *reinterpret_cast<float4*>(out + i) = r;
}

// ================= host launcher =================
extern "C" void kernel_launch(void* const* d_in, const int* in_sizes, int n_in,
                              void* d_out, int out_size)
{
    const float* hidden = (const float*)d_in[0];
    const float* feat   = (const float*)d_in[1];
    const float* bank   = (const float*)d_in[2];
    // d_in[3] = item_seq_len (unused by reference outputs)
    const float* ln_g   = (const float*)d_in[4];
    const float* ln_b   = (const float*)d_in[5];
    const float* fp_w1  = (const float*)d_in[6];
    const float* fp_b1  = (const float*)d_in[7];
    const float* fp_w2  = (const float*)d_in[8];
    const float* fp_b2  = (const float*)d_in[9];
    const float* r_w1   = (const float*)d_in[10];
    const float* r_b1   = (const float*)d_in[11];
    const float* r_w2   = (const float*)d_in[12];
    const float* r_b2   = (const float*)d_in[13];
    const float* rr_w   = (const float*)d_in[14];
    const float* rr_b   = (const float*)d_in[15];
    const float* e_w1   = (const float*)d_in[16];
    const float* e_b1   = (const float*)d_in[17];
    const float* e_w2   = (const float*)d_in[18];
    const float* e_b2   = (const float*)d_in[19];
    const float* alpha  = (const float*)d_in[20];
    float* out = (float*)d_out;

    float *p_hn, *p_H1;
    cudaGetSymbolAddress((void**)&p_hn, g_hnorm);
    cudaGetSymbolAddress((void**)&p_H1, g_H1);

    cudaFuncSetAttribute(k_expert_mma<1>, cudaFuncAttributeMaxDynamicSharedMemorySize, EXP_SMEM_BYTES);
    cudaFuncSetAttribute(k_expert_mma<2>, cudaFuncAttributeMaxDynamicSharedMemorySize, EXP_SMEM_BYTES);

    // K1: layernorm -> g_hnorm, zero stage_out, reset counters/flags
    k_layernorm<<<NTOK, 256>>>(hidden, ln_g, ln_b, out);

    // K2: P1 | XA1 | XA2 | (Wc, cc) — tf32 mma, ~777 active CTAs
    k_mma_router<<<dim3(NTOK / 128, 4, 4), 256>>>(
        bank, fp_w1, fp_b1, fp_w2, fp_b2, r_w1, r_b1);

    // K4b: RH = gelu(P1 @ Wc + cc + XA1 + XA2) — tf32 mma
    k_4b_mma<<<dim3(NTOK / 128, 4), 256>>>();

    // K5: logits, top-2 softmax + ambiguity flagging, dispatch
    k_router<<<NTOK / 8, 256>>>(r_w2, r_b2, feat, rr_w, rr_b, out);

    // K5b: exact fp32 recompute + dispatch for flagged tokens
    k_fallback<<<32, 256>>>(bank, fp_w1, fp_b1, fp_w2, fp_b2,
                            r_w1, r_b1, r_w2, r_b2, out);

    // K6: per-expert gathered GEMM1 (mma.sync tf32, gelu) -> g_H1
    k_expert_mma<1><<<dim3(NTOK / 128, E_HID / 64, N_EXPERTS), 256, EXP_SMEM_BYTES>>>(
        p_hn, e_w1, e_b1, p_H1, D_MODEL, E_HID);

    // K7: per-expert GEMM2 (mma.sync tf32), gate-weighted atomic accumulate
    k_expert_mma<2><<<dim3(NTOK / 128, D_MODEL / 64, N_EXPERTS), 256, EXP_SMEM_BYTES>>>(
        p_H1, e_w2, e_b2, out + OFF_STAGE, E_HID, D_MODEL);

    // K8: next_hidden = hidden + alpha * stage_out
    k_finalize<<<(NTOK * D_MODEL) / (256 * 4), 256>>>(hidden, alpha, out);
}

// round 15
// speedup vs baseline: 1.9381x; 1.9381x over previous
#include <cuda_runtime.h>
#include <math.h>
#include <stdint.h>

// ---------------- problem constants ----------------
#define NTOK      8192            // B*S = 4*2048
#define D_MODEL   1024
#define N_EXPERTS 8
#define N_FEAT    16
#define RAW_FEAT  512
#define PROJ_DIM  256
#define R_IN      1280
#define R_HID     256
#define E_HID     256

// output layout (floats) : next_hidden | stage_out | gate | scaled_logits | group | rule
#define OFF_STAGE 8388608ull
#define OFF_GATE  16777216ull
#define OFF_SLOG  16842752ull
#define OFF_GRP   16908288ull
#define OFF_RULE  16941056ull

typedef unsigned long long ull;

// ---------------- device scratch (no allocations allowed) ----------------
__device__ float g_hnorm[(size_t)NTOK * D_MODEL];
__device__ float g_P1   [(size_t)NTOK * PROJ_DIM];
__device__ float g_XA1  [(size_t)NTOK * R_HID];
__device__ float g_XA2  [(size_t)NTOK * R_HID];
__device__ float g_RHs  [(size_t)NTOK * R_HID];
__device__ float g_Wc   [PROJ_DIM * R_HID];
__device__ float g_cc   [R_HID];
__device__ float g_H1   [(size_t)N_EXPERTS * NTOK * E_HID];
__device__ int   g_tok  [N_EXPERTS * NTOK];
__device__ float g_wt   [N_EXPERTS * NTOK];
__device__ int   g_cnt  [N_EXPERTS];

// ---------------- helpers ----------------
__device__ __forceinline__ float gelu_tanh(float x) {
    float x3 = x * x * x;
    return 0.5f * x * (1.0f + tanhf(0.7978845608028654f * (x + 0.044715f * x3)));
}
// packed dual-fp32 FMA (Blackwell f32x2)
__device__ __forceinline__ ull ffma2(ull a, ull b, ull c) {
    ull d;
    asm("fma.rn.f32x2 %0, %1, %2, %3;" : "=l"(d) : "l"(a), "l"(b), "l"(c));
    return d;
}
__device__ __forceinline__ ull pack2(float x) {
    ull d;
    asm("mov.b64 %0, {%1, %1};" : "=l"(d) : "f"(x));
    return d;
}
__device__ __forceinline__ float2 unpack2(ull v) {
    float lo, hi;
    asm("mov.b64 {%0, %1}, %2;" : "=f"(lo), "=f"(hi) : "l"(v));
    return make_float2(lo, hi);
}

// ================= K1: layernorm + init =================
__global__ __launch_bounds__(256) void k_layernorm(
    const float* __restrict__ hidden,
    const float* __restrict__ ln_g,
    const float* __restrict__ ln_b,
    float* __restrict__ out)
{
    int t   = blockIdx.x;
    int tid = threadIdx.x;
    const float* x = hidden + (size_t)t * D_MODEL;

    float v[4], s = 0.f, s2 = 0.f;
#pragma unroll
    for (int j = 0; j < 4; j++) {
        v[j] = x[tid + 256 * j];
        s  += v[j];
        s2 += v[j] * v[j];
    }
#pragma unroll
    for (int o = 16; o; o >>= 1) {
        s  += __shfl_down_sync(0xffffffffu, s,  o);
        s2 += __shfl_down_sync(0xffffffffu, s2, o);
    }
    __shared__ float ps[8], ps2[8];
    __shared__ float mu_s, rs_s;
    int w = tid >> 5, l = tid & 31;
    if (l == 0) { ps[w] = s; ps2[w] = s2; }
    __syncthreads();
    if (tid == 0) {
        float S = 0.f, S2 = 0.f;
#pragma unroll
        for (int i = 0; i < 8; i++) { S += ps[i]; S2 += ps2[i]; }
        float mu  = S * (1.0f / D_MODEL);
        float var = S2 * (1.0f / D_MODEL) - mu * mu;
        mu_s = mu;
        rs_s = rsqrtf(var + 1e-5f);
    }
    __syncthreads();
    float mu = mu_s, rs = rs_s;
#pragma unroll
    for (int j = 0; j < 4; j++) {
        int d = tid + 256 * j;
        float hn = (v[j] - mu) * rs * ln_g[d] + ln_b[d];
        g_hnorm[(size_t)t * D_MODEL + d] = hn;
        out[OFF_STAGE + (size_t)t * D_MODEL + d] = 0.0f;
    }
    if (t == 0 && tid < N_EXPERTS) g_cnt[tid] = 0;
}

// ================= 128x128x8 double-buffered core, packed f32x2 FMA =================
// Aptr: thread-specific &A[row][akq] (row fixed, advance by k). Bptr: &B[bkr][n0+bnc].
// acc2[i][j2]: rows (i<4: ty*4+i, i>=4: 64+ty*4+i-4), col-pairs (j2<2: tx*4+2*j2, j2>=2: 64+tx*4+2*(j2-2)).
__device__ __forceinline__ void core128_x2(
    const float* __restrict__ Aptr, const float* __restrict__ Bptr,
    int ldb, int K,
    float As[2][8][128], float Bs[2][8][128],
    ull acc2[8][4])
{
    const int t = threadIdx.x;
    const int arow = t >> 1, akq = (t & 1) * 4;
    const int bkr  = t >> 5, bnc = (t & 31) * 4;
    const int ty = t >> 4, tx = t & 15;
    (void)arow;

    {
        float4 av = *reinterpret_cast<const float4*>(Aptr);
        float4 bv = *reinterpret_cast<const float4*>(Bptr);
        As[0][akq + 0][t >> 1] = av.x;
        As[0][akq + 1][t >> 1] = av.y;
        As[0][akq + 2][t >> 1] = av.z;
        As[0][akq + 3][t >> 1] = av.w;
        *reinterpret_cast<float4*>(&Bs[0][bkr][bnc]) = bv;
    }
    __syncthreads();

#pragma unroll
    for (int i = 0; i < 8; i++)
#pragma unroll
        for (int j = 0; j < 4; j++) acc2[i][j] = 0ull;

    int buf = 0;
    for (int k0 = 8; k0 < K; k0 += 8) {
        float4 av2 = *reinterpret_cast<const float4*>(Aptr + k0);
        float4 bv2 = *reinterpret_cast<const float4*>(Bptr + (size_t)k0 * ldb);
#pragma unroll
        for (int kk = 0; kk < 8; kk++) {
            float a[8];
            *reinterpret_cast<float4*>(&a[0]) = *reinterpret_cast<const float4*>(&As[buf][kk][ty * 4]);
            *reinterpret_cast<float4*>(&a[4]) = *reinterpret_cast<const float4*>(&As[buf][kk][ty * 4 + 64]);
            ulonglong2 q0 = *reinterpret_cast<const ulonglong2*>(&Bs[buf][kk][tx * 4]);
            ulonglong2 q1 = *reinterpret_cast<const ulonglong2*>(&Bs[buf][kk][tx * 4 + 64]);
            ull b2[4] = {q0.x, q0.y, q1.x, q1.y};
#pragma unroll
            for (int i = 0; i < 8; i++) {
                ull a2 = pack2(a[i]);
                acc2[i][0] = ffma2(a2, b2[0], acc2[i][0]);
                acc2[i][1] = ffma2(a2, b2[1], acc2[i][1]);
                acc2[i][2] = ffma2(a2, b2[2], acc2[i][2]);
                acc2[i][3] = ffma2(a2, b2[3], acc2[i][3]);
            }
        }
        int nb = buf ^ 1;
        As[nb][akq + 0][t >> 1] = av2.x;
        As[nb][akq + 1][t >> 1] = av2.y;
        As[nb][akq + 2][t >> 1] = av2.z;
        As[nb][akq + 3][t >> 1] = av2.w;
        *reinterpret_cast<float4*>(&Bs[nb][bkr][bnc]) = bv2;
        __syncthreads();
        buf = nb;
    }
#pragma unroll
    for (int kk = 0; kk < 8; kk++) {
        float a[8];
        *reinterpret_cast<float4*>(&a[0]) = *reinterpret_cast<const float4*>(&As[buf][kk][ty * 4]);
        *reinterpret_cast<float4*>(&a[4]) = *reinterpret_cast<const float4*>(&As[buf][kk][ty * 4 + 64]);
        ulonglong2 q0 = *reinterpret_cast<const ulonglong2*>(&Bs[buf][kk][tx * 4]);
        ulonglong2 q1 = *reinterpret_cast<const ulonglong2*>(&Bs[buf][kk][tx * 4 + 64]);
        ull b2[4] = {q0.x, q0.y, q1.x, q1.y};
#pragma unroll
        for (int i = 0; i < 8; i++) {
            ull a2 = pack2(a[i]);
            acc2[i][0] = ffma2(a2, b2[0], acc2[i][0]);
            acc2[i][1] = ffma2(a2, b2[1], acc2[i][1]);
            acc2[i][2] = ffma2(a2, b2[2], acc2[i][2]);
            acc2[i][3] = ffma2(a2, b2[3], acc2[i][3]);
        }
    }
}

// unpack row i of acc2 into x[8] (cols tx*4..+3 and 64+tx*4..+3)
#define UNPACK_ROW(acc2, i, x) do {                          \
        float2 p0 = unpack2((acc2)[i][0]);                   \
        float2 p1 = unpack2((acc2)[i][1]);                   \
        float2 p2 = unpack2((acc2)[i][2]);                   \
        float2 p3 = unpack2((acc2)[i][3]);                   \
        (x)[0] = p0.x; (x)[1] = p0.y; (x)[2] = p1.x; (x)[3] = p1.y; \
        (x)[4] = p2.x; (x)[5] = p2.y; (x)[6] = p3.x; (x)[7] = p3.y; \
    } while (0)

// ================= K2fused: multiplexed router GEMMs (fp32-exact, f32x2 core) =================
// z=0: P1  = gelu(bank @ fp_w1 + fp_b1)
// z=1: XA1 = hnorm[:, :512]  @ r_w1[0:512]   + r_b1
// z=2: XA2 = hnorm[:, 512:]  @ r_w1[512:1024]
// z=3: Wc  = fp_w2 @ r_w1[1024:] (bx<2); cc = fp_b2 @ r_w1[1024:] (bx==2,by==0)
__global__ __launch_bounds__(256, 2) void k_fused(
    const float* __restrict__ bank,
    const float* __restrict__ fp_w1, const float* __restrict__ fp_b1,
    const float* __restrict__ fp_w2, const float* __restrict__ fp_b2,
    const float* __restrict__ r_w1,  const float* __restrict__ r_b1)
{
    __shared__ float As[2][8][128];
    __shared__ float Bs[2][8][128];
    const int z  = blockIdx.z;
    const int bx = blockIdx.x, by = blockIdx.y;
    const int m0 = bx * 128, n0 = by * 128;
    const int t = threadIdx.x;
    const int ty = t >> 4, tx = t & 15;

    const float* A; int lda; const float* B; const float* bias;
    float* C; int K; int act;
    if (z == 0) {
        A = bank; lda = RAW_FEAT; B = fp_w1; bias = fp_b1;
        C = g_P1; K = RAW_FEAT; act = 1;
    } else if (z == 1) {
        A = g_hnorm; lda = D_MODEL; B = r_w1; bias = r_b1;
        C = g_XA1; K = 512; act = 0;
    } else if (z == 2) {
        A = g_hnorm + 512; lda = D_MODEL; B = r_w1 + 512 * R_HID; bias = nullptr;
        C = g_XA2; K = 512; act = 0;
    } else {
        if (bx == 2 && by == 0) {
            int j = t;
            float s = 0.f;
            for (int k = 0; k < PROJ_DIM; k++)
                s = fmaf(fp_b2[k], r_w1[(size_t)(D_MODEL + k) * R_HID + j], s);
            g_cc[j] = s;
            return;
        }
        if (bx >= 2) return;
        A = fp_w2; lda = PROJ_DIM; B = r_w1 + (size_t)D_MODEL * R_HID; bias = nullptr;
        C = g_Wc; K = PROJ_DIM; act = 0;
    }

    const int arow = t >> 1, akq = (t & 1) * 4;
    const int bkr  = t >> 5, bnc = (t & 31) * 4;
    const float* Aptr = A + (size_t)(m0 + arow) * lda + akq;
    const float* Bptr = B + (size_t)bkr * R_HID + n0 + bnc;

    ull acc2[8][4];
    core128_x2(Aptr, Bptr, R_HID, K, As, Bs, acc2);

    float bb[8];
#pragma unroll
    for (int j = 0; j < 4; j++) {
        bb[j]     = bias ? bias[n0 + tx * 4 + j]      : 0.f;
        bb[4 + j] = bias ? bias[n0 + 64 + tx * 4 + j] : 0.f;
    }
#pragma unroll
    for (int i = 0; i < 8; i++) {
        int m = m0 + (i >> 2) * 64 + ty * 4 + (i & 3);
        float x[8];
        UNPACK_ROW(acc2, i, x);
        float4 v0, v1;
        float* p0 = &v0.x;
        float* p1 = &v1.x;
#pragma unroll
        for (int j = 0; j < 4; j++) {
            float x0 = x[j] + bb[j];
            float x1 = x[4 + j] + bb[4 + j];
            if (act) { x0 = gelu_tanh(x0); x1 = gelu_tanh(x1); }
            p0[j] = x0; p1[j] = x1;
        }
        *reinterpret_cast<float4*>(&C[(size_t)m * R_HID + n0 + tx * 4])      = v0;
        *reinterpret_cast<float4*>(&C[(size_t)m * R_HID + n0 + 64 + tx * 4]) = v1;
    }
}

// ================= K4b: RH = gelu(P1 @ Wc + cc + XA1 + XA2) =================
__global__ __launch_bounds__(256, 2) void k_4b()
{
    __shared__ float As[2][8][128];
    __shared__ float Bs[2][8][128];
    const int m0 = blockIdx.x * 128, n0 = blockIdx.y * 128;
    const int t = threadIdx.x;
    const int ty = t >> 4, tx = t & 15;
    const int arow = t >> 1, akq = (t & 1) * 4;
    const int bkr  = t >> 5, bnc = (t & 31) * 4;

    const float* Aptr = g_P1 + (size_t)(m0 + arow) * PROJ_DIM + akq;
    const float* Bptr = g_Wc + (size_t)bkr * R_HID + n0 + bnc;

    ull acc2[8][4];
    core128_x2(Aptr, Bptr, R_HID, PROJ_DIM, As, Bs, acc2);

    float cc0[4], cc1[4];
#pragma unroll
    for (int j = 0; j < 4; j++) {
        cc0[j] = g_cc[n0 + tx * 4 + j];
        cc1[j] = g_cc[n0 + 64 + tx * 4 + j];
    }
#pragma unroll
    for (int i = 0; i < 8; i++) {
        int m = m0 + (i >> 2) * 64 + ty * 4 + (i & 3);
        float x[8];
        UNPACK_ROW(acc2, i, x);
        float4 u0 = *reinterpret_cast<const float4*>(&g_XA1[(size_t)m * R_HID + n0 + tx * 4]);
        float4 u1 = *reinterpret_cast<const float4*>(&g_XA1[(size_t)m * R_HID + n0 + 64 + tx * 4]);
        float4 w0 = *reinterpret_cast<const float4*>(&g_XA2[(size_t)m * R_HID + n0 + tx * 4]);
        float4 w1 = *reinterpret_cast<const float4*>(&g_XA2[(size_t)m * R_HID + n0 + 64 + tx * 4]);
        const float* pu0 = &u0.x;
        const float* pu1 = &u1.x;
        const float* pw0 = &w0.x;
        const float* pw1 = &w1.x;
        float4 v0, v1;
        float* p0 = &v0.x;
        float* p1 = &v1.x;
#pragma unroll
        for (int j = 0; j < 4; j++) {
            p0[j] = gelu_tanh(x[j]     + cc0[j] + pu0[j] + pw0[j]);
            p1[j] = gelu_tanh(x[4 + j] + cc1[j] + pu1[j] + pw1[j]);
        }
        *reinterpret_cast<float4*>(&g_RHs[(size_t)m * R_HID + n0 + tx * 4])      = v0;
        *reinterpret_cast<float4*>(&g_RHs[(size_t)m * R_HID + n0 + 64 + tx * 4]) = v1;
    }
}

// ================= K5: router logits, top-2 softmax, small outputs, dispatch =================
__global__ __launch_bounds__(256) void k_router(
    const float* __restrict__ r_w2, const float* __restrict__ r_b2,
    const float* __restrict__ feat,
    const float* __restrict__ rr_w, const float* __restrict__ rr_b,
    float* __restrict__ out)
{
    int w = threadIdx.x >> 5, l = threadIdx.x & 31;
    int t = blockIdx.x * 8 + w;
    const float* rh = g_RHs + (size_t)t * R_HID;

    float acc[8] = {};
    for (int k = l; k < R_HID; k += 32) {
        float v = rh[k];
#pragma unroll
        for (int e = 0; e < 8; e++) acc[e] = fmaf(v, r_w2[k * 8 + e], acc[e]);
    }
#pragma unroll
    for (int o = 16; o; o >>= 1)
#pragma unroll
        for (int e = 0; e < 8; e++) acc[e] += __shfl_down_sync(0xffffffffu, acc[e], o);

    if (l == 0) {
        float lg[8];
#pragma unroll
        for (int e = 0; e < 8; e++) lg[e] = acc[e] + r_b2[e];
        int i1 = 0; float m1 = lg[0];
#pragma unroll
        for (int e = 1; e < 8; e++) if (lg[e] > m1) { m1 = lg[e]; i1 = e; }
        float m2 = -3.4e38f;
#pragma unroll
        for (int e = 0; e < 8; e++) if (e != i1 && lg[e] > m2) m2 = lg[e];
        float Z = 0.f, g[8];
#pragma unroll
        for (int e = 0; e < 8; e++) {
            if (lg[e] >= m2) { g[e] = expf(lg[e] - m1); Z += g[e]; }
            else g[e] = 0.f;
        }
        float invZ = 1.0f / Z;
#pragma unroll
        for (int e = 0; e < 8; e++) {
            g[e] *= invZ;
            out[OFF_GATE + (size_t)t * 8 + e] = g[e];
            out[OFF_SLOG + (size_t)t * 8 + e] = lg[e];
        }
#pragma unroll
        for (int gi = 0; gi < 4; gi++)
            out[OFF_GRP + (size_t)t * 4 + gi] = g[2 * gi] + g[2 * gi + 1];
        float fv[16];
#pragma unroll
        for (int i = 0; i < 16; i++) fv[i] = feat[(size_t)t * 16 + i];
#pragma unroll
        for (int e = 0; e < 8; e++) {
            float r = rr_b[e];
#pragma unroll
            for (int i = 0; i < 16; i++) r = fmaf(fv[i], rr_w[i * 8 + e], r);
            out[OFF_RULE + (size_t)t * 8 + e] = r;
        }
#pragma unroll
        for (int e = 0; e < 8; e++) {
            if (g[e] > 0.f) {
                int p = atomicAdd(&g_cnt[e], 1);
                g_tok[e * NTOK + p] = t;
                g_wt [e * NTOK + p] = g[e];
            }
        }
    }
}

// ================= expert GEMMs, f32x2 core =================
// MODE 1: H1 = gelu(hnorm[gathered] @ e_w1 + b1)   (K=1024, N=256, compacted store)
// MODE 2: stage_out[tok] += wt * (H1 @ e_w2 + b2)  (K=256,  N=1024, atomic scatter)
template<int MODE>
__global__ __launch_bounds__(256, 2) void k_expert_x2(
    const float* __restrict__ Asrc, const float* __restrict__ Bsrc,
    const float* __restrict__ bias, float* __restrict__ C,
    int K, int Ntot)
{
    __shared__ float As[2][8][128];
    __shared__ float Bs[2][8][128];
    __shared__ int   tok_s[128];
    __shared__ float wt_s[128];

    const int t  = threadIdx.x;
    const int e  = blockIdx.z;
    const int m0 = blockIdx.x * 128;
    const int n0 = blockIdx.y * 128;
    const int M  = g_cnt[e];
    if (m0 >= M) return;

    const float* Ae = (MODE == 1) ? Asrc : Asrc + (size_t)e * NTOK * K;
    const float* Be = Bsrc + (size_t)e * K * Ntot;
    const float* be = bias + e * Ntot + n0;

    if (t < 128) {
        int idx = e * NTOK + min(m0 + t, M - 1);
        tok_s[t] = g_tok[idx];
        if (MODE == 2) wt_s[t] = g_wt[idx];
    }
    __syncthreads();

    const int arow = t >> 1, akq = (t & 1) * 4;
    const int bkr  = t >> 5, bnc = (t & 31) * 4;
    const int ty = t >> 4, tx = t & 15;

    size_t rowi = (MODE == 1) ? (size_t)tok_s[arow]
                              : (size_t)min(m0 + arow, M - 1);
    const float* Aptr = Ae + rowi * (size_t)K + akq;
    const float* Bptr = Be + (size_t)bkr * Ntot + n0 + bnc;

    ull acc2[8][4];
    core128_x2(Aptr, Bptr, Ntot, K, As, Bs, acc2);

    float bb[8];
#pragma unroll
    for (int j = 0; j < 4; j++) {
        bb[j]     = be[tx * 4 + j];
        bb[4 + j] = be[64 + tx * 4 + j];
    }
#pragma unroll
    for (int i = 0; i < 8; i++) {
        int rl = (i >> 2) * 64 + ty * 4 + (i & 3);
        int m  = m0 + rl;
        if (m < M) {
            float x[8];
            UNPACK_ROW(acc2, i, x);
            if (MODE == 1) {
                float4 v0, v1;
                float* p0 = &v0.x;
                float* p1 = &v1.x;
#pragma unroll
                for (int j = 0; j < 4; j++) {
                    p0[j] = gelu_tanh(x[j] + bb[j]);
                    p1[j] = gelu_tanh(x[4 + j] + bb[4 + j]);
                }
                float* dst = C + ((size_t)e * NTOK + m) * Ntot + n0;
                *reinterpret_cast<float4*>(&dst[tx * 4])      = v0;
                *reinterpret_cast<float4*>(&dst[64 + tx * 4]) = v1;
            } else {
                int   tok = tok_s[rl];
                float wgt = wt_s[rl];
                float* dst = C + (size_t)tok * D_MODEL + n0;
#pragma unroll
                for (int j = 0; j < 4; j++) {
                    atomicAdd(&dst[tx * 4 + j],      (x[j]     + bb[j])     * wgt);
                    atomicAdd(&dst[64 + tx * 4 + j], (x[4 + j] + bb[4 + j]) * wgt);
                }
            }
        }
    }
}

// ================= K8: next_hidden = hidden + alpha * stage_out =================
__global__ __launch_bounds__(256) void k_finalize(
    const float* __restrict__ hidden,
    const float* __restrict__ alpha,
    float* __restrict__ out)
{
    size_t i = ((size_t)blockIdx.x * 256 + threadIdx.x) * 4;
    float a = alpha[0];
    float4 h = *reinterpret_cast<const float4*>(hidden + i);
    float4 s = *reinterpret_cast<const float4*>(out + OFF_STAGE + i);
    float4 r;
    r.x = h.x + a * s.x;
    r.y = h.y + a * s.y;
    r.z = h.z + a * s.z;
    r.w = h.w + a * s.w;
    *reinterpret_cast<float4*>(out + i) = r;
}

// ================= host launcher =================
extern "C" void kernel_launch(void* const* d_in, const int* in_sizes, int n_in,
                              void* d_out, int out_size)
{
    const float* hidden = (const float*)d_in[0];
    const float* feat   = (const float*)d_in[1];
    const float* bank   = (const float*)d_in[2];
    // d_in[3] = item_seq_len (unused by reference outputs)
    const float* ln_g   = (const float*)d_in[4];
    const float* ln_b   = (const float*)d_in[5];
    const float* fp_w1  = (const float*)d_in[6];
    const float* fp_b1  = (const float*)d_in[7];
    const float* fp_w2  = (const float*)d_in[8];
    const float* fp_b2  = (const float*)d_in[9];
    const float* r_w1   = (const float*)d_in[10];
    const float* r_b1   = (const float*)d_in[11];
    const float* r_w2   = (const float*)d_in[12];
    const float* r_b2   = (const float*)d_in[13];
    const float* rr_w   = (const float*)d_in[14];
    const float* rr_b   = (const float*)d_in[15];
    const float* e_w1   = (const float*)d_in[16];
    const float* e_b1   = (const float*)d_in[17];
    const float* e_w2   = (const float*)d_in[18];
    const float* e_b2   = (const float*)d_in[19];
    const float* alpha  = (const float*)d_in[20];
    float* out = (float*)d_out;

    float *p_hn, *p_H1;
    cudaGetSymbolAddress((void**)&p_hn, g_hnorm);
    cudaGetSymbolAddress((void**)&p_H1, g_H1);

    // K1: layernorm -> g_hnorm, zero stage_out, reset counters
    k_layernorm<<<NTOK, 256>>>(hidden, ln_g, ln_b, out);

    // K2fused: P1 | XA1 | XA2 | (Wc, cc) — f32x2 cores, ~390 active CTAs
    k_fused<<<dim3(NTOK / 128, 2, 4), 256>>>(
        bank, fp_w1, fp_b1, fp_w2, fp_b2, r_w1, r_b1);

    // K4b: RH = gelu(P1 @ Wc + cc + XA1 + XA2)
    k_4b<<<dim3(NTOK / 128, 2), 256>>>();

    // K5: logits, top-2 softmax (fp32-exact), small outputs, expert dispatch
    k_router<<<NTOK / 8, 256>>>(r_w2, r_b2, feat, rr_w, rr_b, out);

    // K6: per-expert gathered GEMM1 (f32x2, gelu) -> g_H1
    k_expert_x2<1><<<dim3(NTOK / 128, E_HID / 128, N_EXPERTS), 256>>>(
        p_hn, e_w1, e_b1, p_H1, D_MODEL, E_HID);

    // K7: per-expert GEMM2 (f32x2), gate-weighted atomic accumulate
    k_expert_x2<2><<<dim3(NTOK / 128, D_MODEL / 128, N_EXPERTS), 256>>>(
        p_H1, e_w2, e_b2, out + OFF_STAGE, E_HID, D_MODEL);

    // K8: next_hidden = hidden + alpha * stage_out
    k_finalize<<<(NTOK * D_MODEL) / (256 * 4), 256>>>(hidden, alpha, out);
}